// round 6
// baseline (speedup 1.0000x reference)
#include <cuda_runtime.h>
#include <cuda_bf16.h>

// input_ids (64,1024) i32 | attention_mask (64,1024) i32 | hashed_vocab (768,30000) f32
// output (64,768) f32 = L2-normalized per-row minhash signatures.
// hv[h,v] = (a_h*v + b_h) mod P with P = 30011 = next_prime(30000).
#define BATCH 64
#define SEQ   1024
#define NH    768
#define VOCAB 30000
#define PRIME 30011u
#define MAPB  30016            // byte map, padded to 4B multiple

__device__ __forceinline__ unsigned modmul(unsigned x, unsigned y) {
    return (x * y) % PRIME;    // products < 2^30; const mod -> mulhi magic
}

__global__ void __launch_bounds__(NH, 1)
minhash_kernel(const int* __restrict__ ids,
               const int* __restrict__ mask,
               const float* __restrict__ hv,
               float* __restrict__ out)
{
    __shared__ unsigned char present[MAPB];   // membership byte map (30 KB)
    __shared__ unsigned s_ainv[NH];
    __shared__ unsigned s_id0[NH];
    __shared__ unsigned s_step[NH];
    __shared__ float    s_sumsq;

    const int b = blockIdx.x;
    const int t = threadIdx.x;
    const int lane  = t & 31;
    const int wbase = t & ~31;                // first hash of this warp

    // ---- 1. zero + build membership byte map ----
    unsigned* pw = reinterpret_cast<unsigned*>(present);
    #pragma unroll
    for (int i = t; i < MAPB / 4; i += NH) pw[i] = 0u;
    if (t == 0) s_sumsq = 0.0f;
    __syncthreads();

    #pragma unroll
    for (int s = t; s < SEQ; s += NH) {
        int id = ids[b * SEQ + s];
        int mk = mask[b * SEQ + s];
        if (mk == 1 && id > 100 && id < VOCAB) present[id] = 1;
    }

    // ---- 2. recover (a,b) for hash t; a^-1 = a^(P-2) mod P (Fermat) ----
    float2 v01 = *reinterpret_cast<const float2*>(hv + (size_t)t * VOCAB);
    unsigned bb = (unsigned)v01.x;
    unsigned aa = (unsigned)v01.y + PRIME - bb;
    if (aa >= PRIME) aa -= PRIME;

    unsigned ainv = 1u, base = aa;
    #pragma unroll
    for (unsigned e = PRIME - 2u; e; e >>= 1u) {   // e = 30009
        if (e & 1u) ainv = modmul(ainv, base);
        base = modmul(base, base);
    }
    s_ainv[t] = ainv;
    s_id0[t]  = modmul(ainv, (PRIME - bb) % PRIME);   // id at m=0
    s_step[t] = (ainv << 5) % PRIME;                  // 32*a^-1 mod P
    __syncthreads();

    // ---- 3. warp-cooperative inverse probing, 4 hashes in flight ----
    // For hash hh: smallest m with present[(id0 + m*ainv) mod P] set.
    // Lane l checks m = 32r + l; ballot -> min. Four independent
    // LDS->VOTE chains per round hide each other's latency.
    unsigned my_m = 0u;
    #pragma unroll 1
    for (int j = 0; j < 8; ++j) {
        unsigned idl[4], stp[4], res[4];
        bool     fin[4];
        #pragma unroll
        for (int k = 0; k < 4; ++k) {
            int hh = wbase + j + 8 * k;
            unsigned av = s_ainv[hh];                // broadcast LDS
            unsigned v  = s_id0 [hh] + (unsigned)(lane * av) % PRIME;
            if (v >= PRIME) v -= PRIME;
            idl[k] = v;
            stp[k] = s_step[hh];
            fin[k] = false;
            res[k] = 0u;
        }
        unsigned mb = 0u;
        #pragma unroll 1
        while (true) {
            unsigned bal[4];
            #pragma unroll
            for (int k = 0; k < 4; ++k)
                bal[k] = __ballot_sync(0xffffffffu, present[idl[k]] != 0);
            #pragma unroll
            for (int k = 0; k < 4; ++k)
                if (!fin[k] && bal[k]) {
                    res[k] = mb + (unsigned)(__ffs(bal[k]) - 1);
                    fin[k] = true;
                }
            if ((fin[0] & fin[1] & fin[2] & fin[3]) != 0) break;
            #pragma unroll
            for (int k = 0; k < 4; ++k) {
                idl[k] += stp[k];
                if (idl[k] >= PRIME) idl[k] -= PRIME;
            }
            mb += 32u;
            if (mb >= (unsigned)MAPB) break;         // unreachable with real data
        }
        // lane j+8k owns hash wbase+j+8k
        #pragma unroll
        for (int k = 0; k < 4; ++k)
            if (lane == j + 8 * k) my_m = res[k];
    }

    // ---- 4. block L2 norm over this batch's 768 signatures ----
    float sv = (float)my_m;
    float part = sv * sv;
    #pragma unroll
    for (int o = 16; o > 0; o >>= 1)
        part += __shfl_xor_sync(0xffffffffu, part, o);
    if (lane == 0) atomicAdd(&s_sumsq, part);
    __syncthreads();

    float norm = sqrtf(s_sumsq);
    out[b * NH + t] = sv / fmaxf(norm, 1e-12f);
}

extern "C" void kernel_launch(void* const* d_in, const int* in_sizes, int n_in,
                              void* d_out, int out_size)
{
    const int*   ids  = (const int*)d_in[0];
    const int*   mask = (const int*)d_in[1];
    const float* hv   = (const float*)d_in[2];
    float*       out  = (float*)d_out;
    (void)in_sizes; (void)n_in; (void)out_size;

    minhash_kernel<<<BATCH, NH>>>(ids, mask, hv, out);
}

// round 7
// speedup vs baseline: 1.0175x; 1.0175x over previous
#include <cuda_runtime.h>
#include <cuda_bf16.h>
#include <cstdint>

// input_ids (64,1024) i32 | attention_mask (64,1024) i32 | hashed_vocab (768,30000) f32
// output (64,768) f32 = L2-normalized per-row minhash signatures.
// hv[h,v] = (a_h*v + b_h) mod P, P = 30011 = next_prime(30000).
//
// Strategy: recover (a,b) from hv[h,0..1]; invert a (Fermat); probe m = 0,1,2,...
// asking whether id = a^-1(m-b) mod P is in the batch's valid-token set
// (shared-memory byte map). First hit = min hash value. Warp-cooperative
// (lane l probes m=32r+l, ballot -> min), 4 hashes in flight, prefetched.
// Each batch is split across a 2-CTA cluster (384 hashes per block); the
// L2-norm partial sums are exchanged through DSMEM.
#define BATCH 64
#define SEQ   1024
#define NH    768
#define HPB   384              // hashes per block (NH/2)
#define VOCAB 30000
#define PRIME 30011u
#define MAPB  30016            // byte map, padded to 4B multiple

__device__ __forceinline__ unsigned modmul(unsigned x, unsigned y) {
    return (x * y) % PRIME;    // products < 2^30; const mod -> mulhi magic
}

__device__ __forceinline__ uint32_t smem_u32(const void* p) {
    uint32_t a;
    asm("{ .reg .u64 t; cvta.to.shared.u64 t, %1; cvt.u32.u64 %0, t; }"
        : "=r"(a) : "l"(p));
    return a;
}

__global__ void __launch_bounds__(NH, 1) __cluster_dims__(2, 1, 1)
minhash_kernel(const int* __restrict__ ids,
               const int* __restrict__ mask,
               const float* __restrict__ hv,
               float* __restrict__ out)
{
    __shared__ unsigned char present[MAPB];   // membership byte map (30 KB)
    __shared__ unsigned s_ainv[HPB];
    __shared__ unsigned s_id0[HPB];
    __shared__ unsigned s_step[HPB];
    __shared__ float    s_sum[2];             // [0]=local partial, [1]=peer

    const int b    = blockIdx.x >> 1;         // batch row
    const int half = blockIdx.x & 1;          // which 384-hash half
    const int t    = threadIdx.x;
    const int lane = t & 31;
    const int warp = t >> 5;                  // 0..23

    // ---- 1. zero + build membership byte map (all 768 threads) ----
    unsigned* pw = reinterpret_cast<unsigned*>(present);
    #pragma unroll
    for (int i = t; i < MAPB / 4; i += NH) pw[i] = 0u;
    if (t == 0) { s_sum[0] = 0.0f; s_sum[1] = 0.0f; }
    __syncthreads();

    #pragma unroll
    for (int s = t; s < SEQ; s += NH) {
        int id = ids[b * SEQ + s];
        int mk = mask[b * SEQ + s];
        if (mk == 1 && id > 100 && id < VOCAB) present[id] = 1;
    }

    // ---- 2. per-hash params for this block's 384 hashes (threads 0..383) ----
    if (t < HPB) {
        int h = half * HPB + t;
        float2 v01 = *reinterpret_cast<const float2*>(hv + (size_t)h * VOCAB);
        unsigned bb = (unsigned)v01.x;
        unsigned aa = (unsigned)v01.y + PRIME - bb;
        if (aa >= PRIME) aa -= PRIME;
        unsigned ainv = 1u, base = aa;
        #pragma unroll
        for (unsigned e = PRIME - 2u; e; e >>= 1u) {   // a^(P-2) mod P
            if (e & 1u) ainv = modmul(ainv, base);
            base = modmul(base, base);
        }
        s_ainv[t] = ainv;
        s_id0[t]  = modmul(ainv, (PRIME - bb) % PRIME);
        s_step[t] = (ainv << 5) % PRIME;               // 32*a^-1 mod P
    }
    __syncthreads();

    // ---- 3. probing: 16 hashes per warp, 4 chains in flight, prefetched ----
    const int wslot = warp * 16;               // this warp's slice in s_* arrays
    unsigned my_m = 0u;
    #pragma unroll 1
    for (int j = 0; j < 4; ++j) {
        unsigned idl[4], stp[4], res[4], val[4];
        bool fin[4];
        #pragma unroll
        for (int k = 0; k < 4; ++k) {
            int hh = wslot + j * 4 + k;
            unsigned av = s_ainv[hh];                    // broadcast LDS
            unsigned v  = s_id0[hh] + (unsigned)(lane * av) % PRIME;
            if (v >= PRIME) v -= PRIME;
            idl[k] = v; stp[k] = s_step[hh];
            fin[k] = false; res[k] = 0u;
            val[k] = present[v];                         // prefetch round 0
        }
        unsigned mb = 0u;
        #pragma unroll 1
        for (;;) {
            // advance + prefetch next round before the vote
            unsigned nidl[4], nval[4];
            #pragma unroll
            for (int k = 0; k < 4; ++k) {
                unsigned v = idl[k] + stp[k];
                if (v >= PRIME) v -= PRIME;
                nidl[k] = v;
                nval[k] = present[v];
            }
            bool alldone = true;
            #pragma unroll
            for (int k = 0; k < 4; ++k) {
                unsigned bal = __ballot_sync(0xffffffffu, val[k] != 0);
                if (!fin[k]) {
                    if (bal) { res[k] = mb + (unsigned)(__ffs(bal) - 1); fin[k] = true; }
                    else alldone = false;
                }
            }
            if (alldone) break;
            #pragma unroll
            for (int k = 0; k < 4; ++k) { idl[k] = nidl[k]; val[k] = nval[k]; }
            mb += 32u;
            if (mb >= (unsigned)MAPB) break;   // unreachable with real data
        }
        #pragma unroll
        for (int k = 0; k < 4; ++k)
            if (lane == j * 4 + k) my_m = res[k];        // lanes 0..15 own results
    }

    // ---- 4. cluster-wide L2 norm over the batch's 768 signatures ----
    float sv = (float)my_m;
    float part = (lane < 16) ? sv * sv : 0.0f;
    #pragma unroll
    for (int o = 16; o > 0; o >>= 1)
        part += __shfl_xor_sync(0xffffffffu, part, o);
    if (lane == 0) atomicAdd(&s_sum[0], part);
    __syncthreads();

    // exchange partial with the peer CTA via DSMEM
    asm volatile("barrier.cluster.arrive;" ::: "memory");
    asm volatile("barrier.cluster.wait;"  ::: "memory");
    if (t == 0) {
        uint32_t myaddr = smem_u32(&s_sum[0]);
        uint32_t peer_rank = 1u - (uint32_t)half;
        uint32_t paddr;
        asm("mapa.shared::cluster.u32 %0, %1, %2;"
            : "=r"(paddr) : "r"(myaddr), "r"(peer_rank));
        float pv;
        asm volatile("ld.shared::cluster.f32 %0, [%1];" : "=f"(pv) : "r"(paddr));
        s_sum[1] = pv;
    }
    __syncthreads();

    float norm = sqrtf(s_sum[0] + s_sum[1]);
    if (lane < 16) {
        int h = half * HPB + warp * 16 + lane;
        out[b * NH + h] = sv / fmaxf(norm, 1e-12f);
    }

    // keep both CTAs resident until peer has read our s_sum
    asm volatile("barrier.cluster.arrive;" ::: "memory");
    asm volatile("barrier.cluster.wait;"  ::: "memory");
}

extern "C" void kernel_launch(void* const* d_in, const int* in_sizes, int n_in,
                              void* d_out, int out_size)
{
    const int*   ids  = (const int*)d_in[0];
    const int*   mask = (const int*)d_in[1];
    const float* hv   = (const float*)d_in[2];
    float*       out  = (float*)d_out;
    (void)in_sizes; (void)n_in; (void)out_size;

    minhash_kernel<<<BATCH * 2, NH>>>(ids, mask, hv, out);
}